// round 10
// baseline (speedup 1.0000x reference)
#include <cuda_runtime.h>

// Problem constants (fixed by the dataset)
#define Nn   50000
#define Ee   800000
#define Gg   512
#define DINc 128

typedef unsigned long long ull;

// ---------- f32x2 packed-FMA helpers (sm_103a) ----------
__device__ __forceinline__ ull fma2(ull a, ull b, ull c) {
    ull d;
    asm("fma.rn.f32x2 %0, %1, %2, %3;" : "=l"(d) : "l"(a), "l"(b), "l"(c));
    return d;
}
__device__ __forceinline__ ull pack2(float x, float y) {
    ull r;
    asm("mov.b64 %0, {%1,%2};" : "=l"(r) : "f"(x), "f"(y));
    return r;
}
__device__ __forceinline__ float2 unpack2(ull v) {
    float2 r;
    asm("mov.b64 {%0,%1}, %2;" : "=f"(r.x), "=f"(r.y) : "l"(v));
    return r;
}
__device__ __forceinline__ float sigmoidf_fast(float x) {
    return __fdividef(1.0f, 1.0f + __expf(-x));
}

// ALL FOUR per-layer edge weight matrices in constant memory (exactly 64 KB).
// Matvec reads are warp-uniform -> LDCU on the uniform port.
__constant__ float cWc[4][4096];

// ---------- scratch (static device globals; row-major e/z) ----------
__device__ float  g_h [(size_t)Nn * 64];
__device__ float  g_e [(size_t)Ee * 64];
__device__ float  g_z [(size_t)Ee * 64];
__device__ float  g_Ah[(size_t)Nn * 64];
__device__ float  g_Bh[(size_t)Nn * 64];
__device__ float  g_Dh[(size_t)Nn * 64];
__device__ float  g_Eh[(size_t)Nn * 64];
__device__ float  g_num[(size_t)Nn * 64];
__device__ float  g_den[(size_t)Nn * 64];
__device__ float  g_hn[(size_t)Nn * 64];
__device__ double g_statsP[32][256];   // striped: [0:64) e_sum [64:128) e_sq [128:192) h_sum [192:256) h_sq
__device__ __align__(16) float g_bnp[256];  // [0:64) mu_e [64:128) inv_e [128:192) mu_h [192:256) inv_h
__device__ float  g_cnt[Gg];

// ---------- initial node embedding: h = nodes_feat @ W_h + b_h ----------
__global__ void __launch_bounds__(256) k_embed_h(const float* __restrict__ x,
                                                 const float* __restrict__ W,
                                                 const float* __restrict__ b) {
    __shared__ __align__(16) float sW[DINc][64];
    __shared__ __align__(16) float sx[16][DINc];
    const int t = threadIdx.x;
    for (int i = t; i < DINc * 64 / 4; i += 256)
        ((float4*)&sW[0][0])[i] = ((const float4*)W)[i];

    const int cq = t & 15, m = t >> 4;
    const float4 bias = ((const float4*)b)[cq];
    const int base = blockIdx.x * 64;

    for (int it = 0; it < 4; it++) {
        const int n0 = base + it * 16;
        __syncthreads();
        for (int i = t; i < 16 * DINc / 4; i += 256) {
            const int row = i >> 5, c4 = i & 31;
            const int n = n0 + row;
            float4 v = make_float4(0.f, 0.f, 0.f, 0.f);
            if (n < Nn) v = ((const float4*)x)[(size_t)n * 32 + c4];
            ((float4*)&sx[row][0])[c4] = v;
        }
        __syncthreads();
        float4 acc = bias;
        #pragma unroll 8
        for (int k = 0; k < DINc; k++) {
            const float xv = sx[m][k];
            const float4 w = ((const float4*)&sW[k][0])[cq];
            acc.x += xv * w.x; acc.y += xv * w.y;
            acc.z += xv * w.z; acc.w += xv * w.w;
        }
        const int n = n0 + m;
        if (n < Nn) ((float4*)g_h)[(size_t)n * 16 + cq] = acc;
    }
}

// ---------- per-layer node GEMMs v2: 2 nodes/thread, f32x2 FMA ----------
extern __shared__ float dsm[];
__global__ void __launch_bounds__(256) k_node_gemm(
        const float* __restrict__ Wa, const float* __restrict__ Wb,
        const float* __restrict__ Wd, const float* __restrict__ We_,
        const float* __restrict__ ba_, const float* __restrict__ bb_,
        const float* __restrict__ bd_, const float* __restrict__ be_) {
    float* sW = dsm;              // 4 * 4096 floats
    float* sx = dsm + 4 * 4096;   // 32 * 64 floats
    const int t = threadIdx.x;

    if (blockIdx.x == 0) {        // zero striped BN stats for this layer
        double* p = &g_statsP[0][0];
        for (int i = t; i < 32 * 256; i += 256) p[i] = 0.0;
    }

    for (int i = t; i < 1024; i += 256) ((float4*)(sW + 0 * 4096))[i] = ((const float4*)Wa)[i];
    for (int i = t; i < 1024; i += 256) ((float4*)(sW + 1 * 4096))[i] = ((const float4*)Wb)[i];
    for (int i = t; i < 1024; i += 256) ((float4*)(sW + 2 * 4096))[i] = ((const float4*)Wd)[i];
    for (int i = t; i < 1024; i += 256) ((float4*)(sW + 3 * 4096))[i] = ((const float4*)We_)[i];

    const int cq = t & 15, m = t >> 4;   // thread handles nodes (2m, 2m+1), channels 4cq..4cq+3
    const float4 bA = ((const float4*)ba_)[cq];
    const float4 bB = ((const float4*)bb_)[cq];
    const float4 bD = ((const float4*)bd_)[cq];
    const float4 bE = ((const float4*)be_)[cq];
    const ull bA0 = pack2(bA.x, bA.y), bA1 = pack2(bA.z, bA.w);
    const ull bB0 = pack2(bB.x, bB.y), bB1 = pack2(bB.z, bB.w);
    const ull bD0 = pack2(bD.x, bD.y), bD1 = pack2(bD.z, bD.w);
    const ull bE0 = pack2(bE.x, bE.y), bE1 = pack2(bE.z, bE.w);
    const int base = blockIdx.x * 128;

    for (int it = 0; it < 4; it++) {
        const int n0 = base + it * 32;
        __syncthreads();
        #pragma unroll
        for (int i = t; i < 512; i += 256) {   // 32 rows x 16 quads
            const int row = i >> 4, c4 = i & 15;
            const int n = n0 + row;
            float4 v = make_float4(0.f, 0.f, 0.f, 0.f);
            if (n < Nn) v = ((const float4*)g_h)[(size_t)n * 16 + c4];
            ((float4*)sx)[row * 16 + c4] = v;
        }
        __syncthreads();
        ull aA[4] = {bA0, bA1, bA0, bA1};
        ull aB[4] = {bB0, bB1, bB0, bB1};
        ull aD[4] = {bD0, bD1, bD0, bD1};
        ull aE[4] = {bE0, bE1, bE0, bE1};
        #pragma unroll 4
        for (int k = 0; k < 64; k++) {
            const float xv0 = sx[(2 * m) * 64 + k];
            const float xv1 = sx[(2 * m + 1) * 64 + k];
            const ull x0 = pack2(xv0, xv0);
            const ull x1 = pack2(xv1, xv1);
            const ull* wA = (const ull*)(sW + 0 * 4096 + k * 64) + 2 * cq;
            const ull* wB = (const ull*)(sW + 1 * 4096 + k * 64) + 2 * cq;
            const ull* wD = (const ull*)(sW + 2 * 4096 + k * 64) + 2 * cq;
            const ull* wE = (const ull*)(sW + 3 * 4096 + k * 64) + 2 * cq;
            const ull wA0 = wA[0], wA1 = wA[1];
            const ull wB0 = wB[0], wB1 = wB[1];
            const ull wD0 = wD[0], wD1 = wD[1];
            const ull wE0 = wE[0], wE1 = wE[1];
            aA[0] = fma2(x0, wA0, aA[0]); aA[1] = fma2(x0, wA1, aA[1]);
            aA[2] = fma2(x1, wA0, aA[2]); aA[3] = fma2(x1, wA1, aA[3]);
            aB[0] = fma2(x0, wB0, aB[0]); aB[1] = fma2(x0, wB1, aB[1]);
            aB[2] = fma2(x1, wB0, aB[2]); aB[3] = fma2(x1, wB1, aB[3]);
            aD[0] = fma2(x0, wD0, aD[0]); aD[1] = fma2(x0, wD1, aD[1]);
            aD[2] = fma2(x1, wD0, aD[2]); aD[3] = fma2(x1, wD1, aD[3]);
            aE[0] = fma2(x0, wE0, aE[0]); aE[1] = fma2(x0, wE1, aE[1]);
            aE[2] = fma2(x1, wE0, aE[2]); aE[3] = fma2(x1, wE1, aE[3]);
        }
        #pragma unroll
        for (int r = 0; r < 2; r++) {
            const int n = n0 + 2 * m + r;
            if (n < Nn) {
                const size_t o = (size_t)n * 16 + cq;
                float2 p0, p1;
                p0 = unpack2(aA[2 * r]); p1 = unpack2(aA[2 * r + 1]);
                ((float4*)g_Ah)[o] = make_float4(p0.x, p0.y, p1.x, p1.y);
                p0 = unpack2(aB[2 * r]); p1 = unpack2(aB[2 * r + 1]);
                ((float4*)g_Bh)[o] = make_float4(p0.x, p0.y, p1.x, p1.y);
                p0 = unpack2(aD[2 * r]); p1 = unpack2(aD[2 * r + 1]);
                ((float4*)g_Dh)[o] = make_float4(p0.x, p0.y, p1.x, p1.y);
                p0 = unpack2(aE[2 * r]); p1 = unpack2(aE[2 * r + 1]);
                ((float4*)g_Eh)[o] = make_float4(p0.x, p0.y, p1.x, p1.y);
                ((float4*)g_num)[o] = make_float4(0.f, 0.f, 0.f, 0.f);
                ((float4*)g_den)[o] = make_float4(0.f, 0.f, 0.f, 0.f);
            }
        }
    }
}

// ---------- edge kernel: CHANNEL-SPLIT (2 passes x 32 channels) for 3 blocks/SM ----------
// MODE 0 (l=0):   e built inline from scalar ef (no e I/O); write z
// MODE 1 (l=1,2): read e; write z
// MODE 2 (l=3):   read e; write NOTHING
template<int MODE>
__global__ void __launch_bounds__(256, 3) k_edge(
        int layer,
        const float* __restrict__ bc_l,
        const int* __restrict__ src, const int* __restrict__ dst,
        const float* __restrict__ enorm,
        const float* __restrict__ ef,
        const float* __restrict__ We_, const float* __restrict__ be_) {
    const int t = blockIdx.x * 256 + threadIdx.x;   // edge id (800000 % 256 == 0)
    const int s = src[t], d = dst[t];
    const float f = (MODE == 0) ? ef[t] : 0.f;
    const float zn = enorm[t];
    const ull* W2 = (const ull*)cWc[layer];   // warp-uniform constant reads (LDCU)
    const float4* e4 = ((const float4*)g_e) + (size_t)t * 16;

    #pragma unroll 1
    for (int p = 0; p < 2; p++) {   // channels 32p .. 32p+31
        // acc = bc + Dh[src] + Eh[dst] for this half
        ull acc[16];
        {
            const float4* bv4 = ((const float4*)bc_l) + p * 8;
            const float4* D4 = ((const float4*)g_Dh) + (size_t)s * 16 + p * 8;
            const float4* E4 = ((const float4*)g_Eh) + (size_t)d * 16 + p * 8;
            #pragma unroll
            for (int q = 0; q < 8; q++) {
                const float4 bv = bv4[q], dv = D4[q], ev = E4[q];
                acc[2 * q]     = pack2(bv.x + dv.x + ev.x, bv.y + dv.y + ev.y);
                acc[2 * q + 1] = pack2(bv.z + dv.z + ev.z, bv.w + dv.w + ev.w);
            }
        }
        // matvec over full e-row for this channel half
        #pragma unroll 2
        for (int q = 0; q < 16; q++) {
            float4 e_q;
            if (MODE == 0) {
                const float4 w = ((const float4*)We_)[q];
                const float4 b = ((const float4*)be_)[q];
                e_q = make_float4(fmaf(f, w.x, b.x), fmaf(f, w.y, b.y),
                                  fmaf(f, w.z, b.z), fmaf(f, w.w, b.w));
            } else {
                e_q = e4[q];
            }
            #pragma unroll
            for (int kk = 0; kk < 4; kk++) {
                const float ek = (kk == 0) ? e_q.x : (kk == 1) ? e_q.y
                               : (kk == 2) ? e_q.z : e_q.w;
                const ull e2 = pack2(ek, ek);
                const ull* w = W2 + (q * 4 + kk) * 32 + p * 16;
                #pragma unroll
                for (int j = 0; j < 16; j++) acc[j] = fma2(e2, w[j], acc[j]);
            }
        }
        // epilogue for this half: z store, sigmoid gate, num/den atomics
        float4* z4 = ((float4*)g_z) + (size_t)t * 16 + p * 8;
        const float4* B4 = ((const float4*)g_Bh) + (size_t)s * 16 + p * 8;
        float4* num4 = ((float4*)g_num) + (size_t)d * 16 + p * 8;
        float4* den4 = ((float4*)g_den) + (size_t)d * 16 + p * 8;
        #pragma unroll
        for (int q = 0; q < 8; q++) {
            const float2 a0 = unpack2(acc[2 * q]);
            const float2 a1 = unpack2(acc[2 * q + 1]);
            float4 sg;
            sg.x = sigmoidf_fast(a0.x); sg.y = sigmoidf_fast(a0.y);
            sg.z = sigmoidf_fast(a1.x); sg.w = sigmoidf_fast(a1.y);
            if (MODE != 2)
                z4[q] = make_float4(a0.x * zn, a0.y * zn, a1.x * zn, a1.y * zn);
            const float4 bq = B4[q];
            atomicAdd(&num4[q], make_float4(sg.x * bq.x, sg.y * bq.y,
                                            sg.z * bq.z, sg.w * bq.w));
            atomicAdd(&den4[q], sg);
        }
    }
}

// ---------- streaming edge update (full-BW pass): e_out = base + relu(BN(z)) ----------
// FIRST=1 (l=0): base = embed(ef)
template<int FIRST>
__global__ void __launch_bounds__(256) k_edge_C(
        const float* __restrict__ ef,
        const float* __restrict__ We_, const float* __restrict__ be_,
        const float* __restrict__ gam, const float* __restrict__ bet) {
    const size_t i = (size_t)blockIdx.x * 256 + threadIdx.x;   // quad idx, Ee*16 exact
    if (i >= (size_t)Ee * 16) return;
    const int q = (int)(i & 15);
    const float4 zv = ((const float4*)g_z)[i];
    float4 base;
    if (FIRST) {
        const float f = ef[i >> 4];
        const float4 w = ((const float4*)We_)[q];
        const float4 b = ((const float4*)be_)[q];
        base = make_float4(fmaf(f, w.x, b.x), fmaf(f, w.y, b.y),
                           fmaf(f, w.z, b.z), fmaf(f, w.w, b.w));
    } else {
        base = ((const float4*)g_e)[i];
    }
    const float4 g4 = ((const float4*)gam)[q];
    const float4 b4 = ((const float4*)bet)[q];
    const float4 mu = ((const float4*)g_bnp)[q];
    const float4 iv = ((const float4*)(g_bnp + 64))[q];
    base.x += fmaxf(0.f, g4.x * (zv.x - mu.x) * iv.x + b4.x);
    base.y += fmaxf(0.f, g4.y * (zv.y - mu.y) * iv.y + b4.y);
    base.z += fmaxf(0.f, g4.z * (zv.z - mu.z) * iv.z + b4.z);
    base.w += fmaxf(0.f, g4.w * (zv.w - mu.w) * iv.w + b4.w);
    ((float4*)g_e)[i] = base;
}

// ---------- BN stats over z (row-major, coalesced; wide grid) ----------
__global__ void __launch_bounds__(256) k_estats() {
    const int c = threadIdx.x & 63;
    const int slot = threadIdx.x >> 6;
    double s = 0.0, q = 0.0;
    for (size_t i = (size_t)blockIdx.x * 4 + slot; i < Ee; i += (size_t)gridDim.x * 4) {
        const float v = g_z[i * 64 + c];
        s += v;
        q += (double)v * (double)v;
    }
    __shared__ double sh[512];
    sh[threadIdx.x] = s;
    sh[256 + threadIdx.x] = q;
    __syncthreads();
    if (threadIdx.x < 64) {
        s = sh[c] + sh[c + 64] + sh[c + 128] + sh[c + 192];
        q = sh[256 + c] + sh[256 + c + 64] + sh[256 + c + 128] + sh[256 + c + 192];
        const int st = blockIdx.x & 31;
        atomicAdd(&g_statsP[st][c], s);
        atomicAdd(&g_statsP[st][64 + c], q);
    }
}

// ---------- node aggregate + graph norm + BN stats over hn ----------
__global__ void __launch_bounds__(256) k_node_B(const float* __restrict__ nnorm) {
    const int c = threadIdx.x & 63;
    const int slot = threadIdx.x >> 6;
    double s = 0.0, q = 0.0;
    for (int n = blockIdx.x * 4 + slot; n < Nn; n += gridDim.x * 4) {
        const size_t idx = (size_t)n * 64 + c;
        const float v = (g_Ah[idx] + g_num[idx] / (g_den[idx] + 1e-6f)) * nnorm[n];
        g_hn[idx] = v;
        s += v;
        q += (double)v * (double)v;
    }
    __shared__ double sh[512];
    sh[threadIdx.x] = s;
    sh[256 + threadIdx.x] = q;
    __syncthreads();
    if (threadIdx.x < 64) {
        s = sh[c] + sh[c + 64] + sh[c + 128] + sh[c + 192];
        q = sh[256 + c] + sh[256 + c + 64] + sh[256 + c + 128] + sh[256 + c + 192];
        const int st = blockIdx.x & 31;
        atomicAdd(&g_statsP[st][128 + c], s);
        atomicAdd(&g_statsP[st][192 + c], q);
    }
}

__global__ void k_finalize() {
    const int c = threadIdx.x;  // 64 threads
    double se = 0.0, qe = 0.0, sh2 = 0.0, qh = 0.0;
    #pragma unroll 4
    for (int st = 0; st < 32; st++) {
        se  += g_statsP[st][c];
        qe  += g_statsP[st][64 + c];
        sh2 += g_statsP[st][128 + c];
        qh  += g_statsP[st][192 + c];
    }
    const double mu_e = se / (double)Ee;
    const double var_e = qe / (double)Ee - mu_e * mu_e;
    g_bnp[c] = (float)mu_e;
    g_bnp[64 + c] = (float)(1.0 / sqrt(var_e + 1e-5));
    const double mu_h = sh2 / (double)Nn;
    const double var_h = qh / (double)Nn - mu_h * mu_h;
    g_bnp[128 + c] = (float)mu_h;
    g_bnp[192 + c] = (float)(1.0 / sqrt(var_h + 1e-5));
}

// ---------- node residual update: h += relu(BN(hn)) ----------
__global__ void __launch_bounds__(256) k_node_C(const float* __restrict__ gam,
                                                const float* __restrict__ bet) {
    const int i = blockIdx.x * 256 + threadIdx.x;
    if (i >= Nn * 16) return;
    const int q = i & 15;
    float4 hv = ((float4*)g_h)[i];
    const float4 hn = ((float4*)g_hn)[i];
    const float4 g4 = ((const float4*)gam)[q];
    const float4 b4 = ((const float4*)bet)[q];
    const float4 mu = ((const float4*)(g_bnp + 128))[q];
    const float4 iv = ((const float4*)(g_bnp + 192))[q];
    hv.x += fmaxf(0.f, g4.x * (hn.x - mu.x) * iv.x + b4.x);
    hv.y += fmaxf(0.f, g4.y * (hn.y - mu.y) * iv.y + b4.y);
    hv.z += fmaxf(0.f, g4.z * (hn.z - mu.z) * iv.z + b4.z);
    hv.w += fmaxf(0.f, g4.w * (hn.w - mu.w) * iv.w + b4.w);
    ((float4*)g_h)[i] = hv;
}

// ---------- readout (fused last-layer node BN+residual) ----------
__global__ void k_zero_out(float* __restrict__ out) {
    const int i = blockIdx.x * 256 + threadIdx.x;   // 128 blocks -> 32768 exact
    out[i] = 0.f;
    if (i < Gg) g_cnt[i] = 0.f;
}

__global__ void __launch_bounds__(256) k_readout(const int* __restrict__ gid,
                                                 const float* __restrict__ gamH,
                                                 const float* __restrict__ betH,
                                                 float* __restrict__ out) {
    const int i = blockIdx.x * 256 + threadIdx.x;   // exact: Nn*16 = 800000
    const int q = i & 15, n = i >> 4;
    float4 hv = ((const float4*)g_h)[i];
    const float4 hn = ((const float4*)g_hn)[i];
    const float4 g4 = ((const float4*)gamH)[q];
    const float4 b4 = ((const float4*)betH)[q];
    const float4 mu = ((const float4*)(g_bnp + 128))[q];
    const float4 iv = ((const float4*)(g_bnp + 192))[q];
    hv.x += fmaxf(0.f, g4.x * (hn.x - mu.x) * iv.x + b4.x);
    hv.y += fmaxf(0.f, g4.y * (hn.y - mu.y) * iv.y + b4.y);
    hv.z += fmaxf(0.f, g4.z * (hn.z - mu.z) * iv.z + b4.z);
    hv.w += fmaxf(0.f, g4.w * (hn.w - mu.w) * iv.w + b4.w);
    const int g = gid[n];
    atomicAdd(((float4*)out) + (size_t)g * 16 + q, hv);
    if (q == 0) atomicAdd(&g_cnt[g], 1.0f);
}

__global__ void k_div(float* __restrict__ out) {
    const int i = blockIdx.x * 256 + threadIdx.x;   // exact 32768
    out[i] /= fmaxf(g_cnt[i >> 6], 1.0f);
}

// =====================================================================
extern "C" void kernel_launch(void* const* d_in, const int* in_sizes, int n_in,
                              void* d_out, int out_size) {
    const float* nodes_feat = (const float*)d_in[0];
    const float* edges_feat = (const float*)d_in[1];
    const float* nnorm      = (const float*)d_in[2];
    const float* enorm      = (const float*)d_in[3];
    const float* W_h        = (const float*)d_in[4];
    const float* b_h        = (const float*)d_in[5];
    const float* W_e        = (const float*)d_in[6];
    const float* b_e        = (const float*)d_in[7];
    const float* Wa         = (const float*)d_in[8];
    const float* ba         = (const float*)d_in[9];
    const float* Wb         = (const float*)d_in[10];
    const float* bb         = (const float*)d_in[11];
    const float* Wc         = (const float*)d_in[12];
    const float* bc         = (const float*)d_in[13];
    const float* Wd         = (const float*)d_in[14];
    const float* bd         = (const float*)d_in[15];
    const float* We         = (const float*)d_in[16];
    const float* be         = (const float*)d_in[17];
    const float* gamma_h    = (const float*)d_in[18];
    const float* beta_h     = (const float*)d_in[19];
    const float* gamma_e    = (const float*)d_in[20];
    const float* beta_e     = (const float*)d_in[21];
    const int*   esrc       = (const int*)d_in[22];
    const int*   edst       = (const int*)d_in[23];
    const int*   gid        = (const int*)d_in[24];
    float* out = (float*)d_out;

    const int dynSmem = 4 * 4096 * 4 + 32 * 64 * 4;
    cudaFuncSetAttribute(k_node_gemm, cudaFuncAttributeMaxDynamicSharedMemorySize, dynSmem);

    // all four Wc layers into constant memory (one 64 KB D2D copy)
    cudaMemcpyToSymbolAsync(cWc, Wc, 4 * 4096 * sizeof(float), 0,
                            cudaMemcpyDeviceToDevice, 0);
    k_embed_h<<<(Nn + 63) / 64, 256>>>(nodes_feat, W_h, b_h);
    k_zero_out<<<128, 256>>>(out);

    const int NG = (Nn + 127) / 128;   // 391 blocks
    const int EG = Ee / 256;           // 3125 blocks, thread-per-edge
    const int EC = (int)(((size_t)Ee * 16 + 255) / 256);
    for (int l = 0; l < 4; l++) {
        k_node_gemm<<<NG, 256, dynSmem>>>(
            Wa + (size_t)l * 4096, Wb + (size_t)l * 4096,
            Wd + (size_t)l * 4096, We + (size_t)l * 4096,
            ba + l * 64, bb + l * 64, bd + l * 64, be + l * 64);

        const float* bcL = bc + l * 64;
        if (l == 0)
            k_edge<0><<<EG, 256>>>(l, bcL, esrc, edst, enorm, edges_feat, W_e, b_e); // <- profiled
        else if (l < 3)
            k_edge<1><<<EG, 256>>>(l, bcL, esrc, edst, enorm, edges_feat, W_e, b_e);
        else
            k_edge<2><<<EG, 256>>>(l, bcL, esrc, edst, enorm, edges_feat, W_e, b_e);

        if (l < 3) k_estats<<<1024, 256>>>();
        k_node_B<<<1024, 256>>>(nnorm);
        k_finalize<<<1, 64>>>();
        if (l < 3) {
            k_node_C<<<(Nn * 16 + 255) / 256, 256>>>(gamma_h + l * 64, beta_h + l * 64);
            if (l == 0)
                k_edge_C<1><<<EC, 256>>>(edges_feat, W_e, b_e,
                                         gamma_e + l * 64, beta_e + l * 64);
            else
                k_edge_C<0><<<EC, 256>>>(edges_feat, W_e, b_e,
                                         gamma_e + l * 64, beta_e + l * 64);
        }
    }

    k_readout<<<Nn * 16 / 256, 256>>>(gid, gamma_h + 3 * 64, beta_h + 3 * 64, out);
    k_div<<<Gg * 64 / 256, 256>>>(out);
}

// round 11
// speedup vs baseline: 1.3577x; 1.3577x over previous
#include <cuda_runtime.h>

// Problem constants (fixed by the dataset)
#define Nn   50000
#define Ee   800000
#define Gg   512
#define DINc 128

typedef unsigned long long ull;

// ---------- f32x2 packed-FMA helpers (sm_103a) ----------
__device__ __forceinline__ ull fma2(ull a, ull b, ull c) {
    ull d;
    asm("fma.rn.f32x2 %0, %1, %2, %3;" : "=l"(d) : "l"(a), "l"(b), "l"(c));
    return d;
}
__device__ __forceinline__ ull pack2(float x, float y) {
    ull r;
    asm("mov.b64 %0, {%1,%2};" : "=l"(r) : "f"(x), "f"(y));
    return r;
}
__device__ __forceinline__ float2 unpack2(ull v) {
    float2 r;
    asm("mov.b64 {%0,%1}, %2;" : "=f"(r.x), "=f"(r.y) : "l"(v));
    return r;
}
__device__ __forceinline__ float sigmoidf_fast(float x) {
    return __fdividef(1.0f, 1.0f + __expf(-x));
}

// ALL FOUR per-layer edge weight matrices in constant memory (exactly 64 KB).
// Matvec reads are warp-uniform -> LDCU on the uniform port.
__constant__ float cWc[4][4096];

// ---------- scratch (static device globals; row-major e/z) ----------
__device__ float  g_h [(size_t)Nn * 64];
__device__ float  g_e [(size_t)Ee * 64];
__device__ float  g_z [(size_t)Ee * 64];
__device__ float  g_Ah[(size_t)Nn * 64];
__device__ float  g_Bh[(size_t)Nn * 64];
__device__ float  g_Dh[(size_t)Nn * 64];
__device__ float  g_Eh[(size_t)Nn * 64];
__device__ float  g_num[(size_t)Nn * 64];
__device__ float  g_den[(size_t)Nn * 64];
__device__ float  g_hn[(size_t)Nn * 64];
__device__ double g_statsP[32][256];   // striped: [0:64) e_sum [64:128) e_sq [128:192) h_sum [192:256) h_sq
__device__ __align__(16) float g_bnp[256];  // [0:64) mu_e [64:128) inv_e [128:192) mu_h [192:256) inv_h
__device__ float  g_cnt[Gg];

// ---------- initial node embedding: h = nodes_feat @ W_h + b_h ----------
__global__ void __launch_bounds__(256) k_embed_h(const float* __restrict__ x,
                                                 const float* __restrict__ W,
                                                 const float* __restrict__ b) {
    __shared__ __align__(16) float sW[DINc][64];
    __shared__ __align__(16) float sx[16][DINc];
    const int t = threadIdx.x;
    for (int i = t; i < DINc * 64 / 4; i += 256)
        ((float4*)&sW[0][0])[i] = ((const float4*)W)[i];

    const int cq = t & 15, m = t >> 4;
    const float4 bias = ((const float4*)b)[cq];
    const int base = blockIdx.x * 64;

    for (int it = 0; it < 4; it++) {
        const int n0 = base + it * 16;
        __syncthreads();
        for (int i = t; i < 16 * DINc / 4; i += 256) {
            const int row = i >> 5, c4 = i & 31;
            const int n = n0 + row;
            float4 v = make_float4(0.f, 0.f, 0.f, 0.f);
            if (n < Nn) v = ((const float4*)x)[(size_t)n * 32 + c4];
            ((float4*)&sx[row][0])[c4] = v;
        }
        __syncthreads();
        float4 acc = bias;
        #pragma unroll 8
        for (int k = 0; k < DINc; k++) {
            const float xv = sx[m][k];
            const float4 w = ((const float4*)&sW[k][0])[cq];
            acc.x += xv * w.x; acc.y += xv * w.y;
            acc.z += xv * w.z; acc.w += xv * w.w;
        }
        const int n = n0 + m;
        if (n < Nn) ((float4*)g_h)[(size_t)n * 16 + cq] = acc;
    }
}

// ---------- per-layer node GEMMs v3: 4 nodes/thread, f32x2 FMA ----------
extern __shared__ float dsm[];
__global__ void __launch_bounds__(256, 2) k_node_gemm(
        const float* __restrict__ Wa, const float* __restrict__ Wb,
        const float* __restrict__ Wd, const float* __restrict__ We_,
        const float* __restrict__ ba_, const float* __restrict__ bb_,
        const float* __restrict__ bd_, const float* __restrict__ be_) {
    float* sW = dsm;              // 4 * 4096 floats
    float* sx = dsm + 4 * 4096;   // 64 * 64 floats
    const int t = threadIdx.x;

    if (blockIdx.x == 0) {        // zero striped BN stats for this layer
        double* p = &g_statsP[0][0];
        for (int i = t; i < 32 * 256; i += 256) p[i] = 0.0;
    }

    for (int i = t; i < 1024; i += 256) ((float4*)(sW + 0 * 4096))[i] = ((const float4*)Wa)[i];
    for (int i = t; i < 1024; i += 256) ((float4*)(sW + 1 * 4096))[i] = ((const float4*)Wb)[i];
    for (int i = t; i < 1024; i += 256) ((float4*)(sW + 2 * 4096))[i] = ((const float4*)Wd)[i];
    for (int i = t; i < 1024; i += 256) ((float4*)(sW + 3 * 4096))[i] = ((const float4*)We_)[i];

    const int cq = t & 15, m = t >> 4;   // thread: nodes 4m..4m+3 of the tile, channels 4cq..4cq+3
    const float4 bA = ((const float4*)ba_)[cq];
    const float4 bB = ((const float4*)bb_)[cq];
    const float4 bD = ((const float4*)bd_)[cq];
    const float4 bE = ((const float4*)be_)[cq];
    const ull bA0 = pack2(bA.x, bA.y), bA1 = pack2(bA.z, bA.w);
    const ull bB0 = pack2(bB.x, bB.y), bB1 = pack2(bB.z, bB.w);
    const ull bD0 = pack2(bD.x, bD.y), bD1 = pack2(bD.z, bD.w);
    const ull bE0 = pack2(bE.x, bE.y), bE1 = pack2(bE.z, bE.w);
    const int base = blockIdx.x * 256;

    for (int it = 0; it < 4; it++) {
        const int n0 = base + it * 64;
        __syncthreads();
        #pragma unroll
        for (int i = t; i < 1024; i += 256) {   // 64 rows x 16 quads
            const int row = i >> 4, c4 = i & 15;
            const int n = n0 + row;
            float4 v = make_float4(0.f, 0.f, 0.f, 0.f);
            if (n < Nn) v = ((const float4*)g_h)[(size_t)n * 16 + c4];
            ((float4*)sx)[row * 16 + c4] = v;
        }
        __syncthreads();
        ull aA[8], aB[8], aD[8], aE[8];   // 4 nodes x 2 channel-pairs
        #pragma unroll
        for (int r = 0; r < 4; r++) {
            aA[2 * r] = bA0; aA[2 * r + 1] = bA1;
            aB[2 * r] = bB0; aB[2 * r + 1] = bB1;
            aD[2 * r] = bD0; aD[2 * r + 1] = bD1;
            aE[2 * r] = bE0; aE[2 * r + 1] = bE1;
        }
        #pragma unroll 4
        for (int k = 0; k < 64; k++) {
            ull x[4];
            #pragma unroll
            for (int r = 0; r < 4; r++) {
                const float xv = sx[(4 * m + r) * 64 + k];
                x[r] = pack2(xv, xv);
            }
            const ull wA0 = ((const ull*)(sW + 0 * 4096 + k * 64))[2 * cq];
            const ull wA1 = ((const ull*)(sW + 0 * 4096 + k * 64))[2 * cq + 1];
            const ull wB0 = ((const ull*)(sW + 1 * 4096 + k * 64))[2 * cq];
            const ull wB1 = ((const ull*)(sW + 1 * 4096 + k * 64))[2 * cq + 1];
            const ull wD0 = ((const ull*)(sW + 2 * 4096 + k * 64))[2 * cq];
            const ull wD1 = ((const ull*)(sW + 2 * 4096 + k * 64))[2 * cq + 1];
            const ull wE0 = ((const ull*)(sW + 3 * 4096 + k * 64))[2 * cq];
            const ull wE1 = ((const ull*)(sW + 3 * 4096 + k * 64))[2 * cq + 1];
            #pragma unroll
            for (int r = 0; r < 4; r++) {
                aA[2 * r] = fma2(x[r], wA0, aA[2 * r]);
                aA[2 * r + 1] = fma2(x[r], wA1, aA[2 * r + 1]);
                aB[2 * r] = fma2(x[r], wB0, aB[2 * r]);
                aB[2 * r + 1] = fma2(x[r], wB1, aB[2 * r + 1]);
                aD[2 * r] = fma2(x[r], wD0, aD[2 * r]);
                aD[2 * r + 1] = fma2(x[r], wD1, aD[2 * r + 1]);
                aE[2 * r] = fma2(x[r], wE0, aE[2 * r]);
                aE[2 * r + 1] = fma2(x[r], wE1, aE[2 * r + 1]);
            }
        }
        #pragma unroll
        for (int r = 0; r < 4; r++) {
            const int n = n0 + 4 * m + r;
            if (n < Nn) {
                const size_t o = (size_t)n * 16 + cq;
                float2 p0, p1;
                p0 = unpack2(aA[2 * r]); p1 = unpack2(aA[2 * r + 1]);
                ((float4*)g_Ah)[o] = make_float4(p0.x, p0.y, p1.x, p1.y);
                p0 = unpack2(aB[2 * r]); p1 = unpack2(aB[2 * r + 1]);
                ((float4*)g_Bh)[o] = make_float4(p0.x, p0.y, p1.x, p1.y);
                p0 = unpack2(aD[2 * r]); p1 = unpack2(aD[2 * r + 1]);
                ((float4*)g_Dh)[o] = make_float4(p0.x, p0.y, p1.x, p1.y);
                p0 = unpack2(aE[2 * r]); p1 = unpack2(aE[2 * r + 1]);
                ((float4*)g_Eh)[o] = make_float4(p0.x, p0.y, p1.x, p1.y);
                ((float4*)g_num)[o] = make_float4(0.f, 0.f, 0.f, 0.f);
                ((float4*)g_den)[o] = make_float4(0.f, 0.f, 0.f, 0.f);
            }
        }
    }
}

// ---------- edge kernel (R8 form) + in-register BN stats of z ----------
// MODE 0 (l=0):   e built inline from scalar ef (no e I/O); write z; stats
// MODE 1 (l=1,2): read e; write z; stats
// MODE 2 (l=3):   read e; write NOTHING
template<int MODE>
__global__ void __launch_bounds__(256) k_edge(
        int layer,
        const float* __restrict__ bc_l,
        const int* __restrict__ src, const int* __restrict__ dst,
        const float* __restrict__ enorm,
        const float* __restrict__ ef,
        const float* __restrict__ We_, const float* __restrict__ be_) {
    __shared__ float sSum[8][64], sSq[8][64];
    const int t = blockIdx.x * 256 + threadIdx.x;   // edge id (800000 % 256 == 0)
    const int s = src[t], d = dst[t];

    // acc = bc + Dh[src] + Eh[dst]
    ull acc[32];
    {
        const float4* D4 = ((const float4*)g_Dh) + (size_t)s * 16;
        const float4* E4 = ((const float4*)g_Eh) + (size_t)d * 16;
        #pragma unroll
        for (int q = 0; q < 16; q++) {
            const float4 bv = ((const float4*)bc_l)[q];
            const float4 dv = D4[q];
            const float4 ev = E4[q];
            acc[2 * q]     = pack2(bv.x + dv.x + ev.x, bv.y + dv.y + ev.y);
            acc[2 * q + 1] = pack2(bv.z + dv.z + ev.z, bv.w + dv.w + ev.w);
        }
    }

    const float f = (MODE == 0) ? ef[t] : 0.f;
    const float4* e4 = ((const float4*)g_e) + (size_t)t * 16;
    const ull* W2 = (const ull*)cWc[layer];   // warp-uniform constant reads (LDCU)

    #pragma unroll 2
    for (int q = 0; q < 16; q++) {
        float4 e_q;
        if (MODE == 0) {
            const float4 w = ((const float4*)We_)[q];
            const float4 b = ((const float4*)be_)[q];
            e_q = make_float4(fmaf(f, w.x, b.x), fmaf(f, w.y, b.y),
                              fmaf(f, w.z, b.z), fmaf(f, w.w, b.w));
        } else {
            e_q = e4[q];
        }
        #pragma unroll
        for (int kk = 0; kk < 4; kk++) {
            const float ek = (kk == 0) ? e_q.x : (kk == 1) ? e_q.y : (kk == 2) ? e_q.z : e_q.w;
            const ull e2 = pack2(ek, ek);
            const ull* w = W2 + (q * 4 + kk) * 32;
            #pragma unroll
            for (int j = 0; j < 32; j++) acc[j] = fma2(e2, w[j], acc[j]);
        }
    }

    // epilogue: z store, sigmoid gate, num/den atomics, in-register z-stats
    const float zn = enorm[t];
    float4* z4 = ((float4*)g_z) + (size_t)t * 16;
    const float4* B4 = ((const float4*)g_Bh) + (size_t)s * 16;
    float4* num4 = ((float4*)g_num) + (size_t)d * 16;
    float4* den4 = ((float4*)g_den) + (size_t)d * 16;
    const int lane = threadIdx.x & 31, wid = threadIdx.x >> 5;

    #pragma unroll
    for (int q = 0; q < 16; q++) {
        const float2 a0 = unpack2(acc[2 * q]);
        const float2 a1 = unpack2(acc[2 * q + 1]);
        float4 sg;
        sg.x = sigmoidf_fast(a0.x); sg.y = sigmoidf_fast(a0.y);
        sg.z = sigmoidf_fast(a1.x); sg.w = sigmoidf_fast(a1.y);
        if (MODE != 2) {
            const float4 zq = make_float4(a0.x * zn, a0.y * zn, a1.x * zn, a1.y * zn);
            z4[q] = zq;
            // warp butterfly: per-channel sum & sumsq across the 32 edges of this warp
            float s0 = zq.x, s1 = zq.y, s2 = zq.z, s3 = zq.w;
            float q0 = s0 * s0, q1 = s1 * s1, q2 = s2 * s2, q3 = s3 * s3;
            #pragma unroll
            for (int off = 16; off; off >>= 1) {
                s0 += __shfl_xor_sync(0xffffffffu, s0, off);
                s1 += __shfl_xor_sync(0xffffffffu, s1, off);
                s2 += __shfl_xor_sync(0xffffffffu, s2, off);
                s3 += __shfl_xor_sync(0xffffffffu, s3, off);
                q0 += __shfl_xor_sync(0xffffffffu, q0, off);
                q1 += __shfl_xor_sync(0xffffffffu, q1, off);
                q2 += __shfl_xor_sync(0xffffffffu, q2, off);
                q3 += __shfl_xor_sync(0xffffffffu, q3, off);
            }
            if (lane == 0) {
                sSum[wid][4 * q + 0] = s0; sSum[wid][4 * q + 1] = s1;
                sSum[wid][4 * q + 2] = s2; sSum[wid][4 * q + 3] = s3;
                sSq [wid][4 * q + 0] = q0; sSq [wid][4 * q + 1] = q1;
                sSq [wid][4 * q + 2] = q2; sSq [wid][4 * q + 3] = q3;
            }
        }
        const float4 bq = B4[q];
        atomicAdd(&num4[q], make_float4(sg.x * bq.x, sg.y * bq.y, sg.z * bq.z, sg.w * bq.w));
        atomicAdd(&den4[q], sg);
    }

    if (MODE != 2) {
        __syncthreads();
        if (threadIdx.x < 128) {
            const int c = threadIdx.x & 63, part = threadIdx.x >> 6;
            float v = 0.f;
            #pragma unroll
            for (int w = 0; w < 8; w++)
                v += part ? sSq[w][c] : sSum[w][c];
            atomicAdd(&g_statsP[blockIdx.x & 31][part * 64 + c], (double)v);
        }
    }
}

// ---------- streaming edge update (full-BW pass): e_out = base + relu(BN(z)) ----------
// FIRST=1 (l=0): base = embed(ef)
template<int FIRST>
__global__ void __launch_bounds__(256) k_edge_C(
        const float* __restrict__ ef,
        const float* __restrict__ We_, const float* __restrict__ be_,
        const float* __restrict__ gam, const float* __restrict__ bet) {
    const size_t i = (size_t)blockIdx.x * 256 + threadIdx.x;   // quad idx, Ee*16 exact
    if (i >= (size_t)Ee * 16) return;
    const int q = (int)(i & 15);
    const float4 zv = ((const float4*)g_z)[i];
    float4 base;
    if (FIRST) {
        const float f = ef[i >> 4];
        const float4 w = ((const float4*)We_)[q];
        const float4 b = ((const float4*)be_)[q];
        base = make_float4(fmaf(f, w.x, b.x), fmaf(f, w.y, b.y),
                           fmaf(f, w.z, b.z), fmaf(f, w.w, b.w));
    } else {
        base = ((const float4*)g_e)[i];
    }
    const float4 g4 = ((const float4*)gam)[q];
    const float4 b4 = ((const float4*)bet)[q];
    const float4 mu = ((const float4*)g_bnp)[q];
    const float4 iv = ((const float4*)(g_bnp + 64))[q];
    base.x += fmaxf(0.f, g4.x * (zv.x - mu.x) * iv.x + b4.x);
    base.y += fmaxf(0.f, g4.y * (zv.y - mu.y) * iv.y + b4.y);
    base.z += fmaxf(0.f, g4.z * (zv.z - mu.z) * iv.z + b4.z);
    base.w += fmaxf(0.f, g4.w * (zv.w - mu.w) * iv.w + b4.w);
    ((float4*)g_e)[i] = base;
}

// ---------- node aggregate + graph norm + BN stats over hn ----------
__global__ void __launch_bounds__(256) k_node_B(const float* __restrict__ nnorm) {
    const int c = threadIdx.x & 63;
    const int slot = threadIdx.x >> 6;
    double s = 0.0, q = 0.0;
    for (int n = blockIdx.x * 4 + slot; n < Nn; n += gridDim.x * 4) {
        const size_t idx = (size_t)n * 64 + c;
        const float v = (g_Ah[idx] + g_num[idx] / (g_den[idx] + 1e-6f)) * nnorm[n];
        g_hn[idx] = v;
        s += v;
        q += (double)v * (double)v;
    }
    __shared__ double sh[512];
    sh[threadIdx.x] = s;
    sh[256 + threadIdx.x] = q;
    __syncthreads();
    if (threadIdx.x < 64) {
        s = sh[c] + sh[c + 64] + sh[c + 128] + sh[c + 192];
        q = sh[256 + c] + sh[256 + c + 64] + sh[256 + c + 128] + sh[256 + c + 192];
        const int st = blockIdx.x & 31;
        atomicAdd(&g_statsP[st][128 + c], s);
        atomicAdd(&g_statsP[st][192 + c], q);
    }
}

__global__ void k_finalize() {
    const int c = threadIdx.x;  // 64 threads
    double se = 0.0, qe = 0.0, sh2 = 0.0, qh = 0.0;
    #pragma unroll 4
    for (int st = 0; st < 32; st++) {
        se  += g_statsP[st][c];
        qe  += g_statsP[st][64 + c];
        sh2 += g_statsP[st][128 + c];
        qh  += g_statsP[st][192 + c];
    }
    const double mu_e = se / (double)Ee;
    const double var_e = qe / (double)Ee - mu_e * mu_e;
    g_bnp[c] = (float)mu_e;
    g_bnp[64 + c] = (float)(1.0 / sqrt(var_e + 1e-5));
    const double mu_h = sh2 / (double)Nn;
    const double var_h = qh / (double)Nn - mu_h * mu_h;
    g_bnp[128 + c] = (float)mu_h;
    g_bnp[192 + c] = (float)(1.0 / sqrt(var_h + 1e-5));
}

// ---------- node residual update: h += relu(BN(hn)) ----------
__global__ void __launch_bounds__(256) k_node_C(const float* __restrict__ gam,
                                                const float* __restrict__ bet) {
    const int i = blockIdx.x * 256 + threadIdx.x;
    if (i >= Nn * 16) return;
    const int q = i & 15;
    float4 hv = ((float4*)g_h)[i];
    const float4 hn = ((float4*)g_hn)[i];
    const float4 g4 = ((const float4*)gam)[q];
    const float4 b4 = ((const float4*)bet)[q];
    const float4 mu = ((const float4*)(g_bnp + 128))[q];
    const float4 iv = ((const float4*)(g_bnp + 192))[q];
    hv.x += fmaxf(0.f, g4.x * (hn.x - mu.x) * iv.x + b4.x);
    hv.y += fmaxf(0.f, g4.y * (hn.y - mu.y) * iv.y + b4.y);
    hv.z += fmaxf(0.f, g4.z * (hn.z - mu.z) * iv.z + b4.z);
    hv.w += fmaxf(0.f, g4.w * (hn.w - mu.w) * iv.w + b4.w);
    ((float4*)g_h)[i] = hv;
}

// ---------- readout (fused last-layer node BN+residual) ----------
__global__ void k_zero_out(float* __restrict__ out) {
    const int i = blockIdx.x * 256 + threadIdx.x;   // 128 blocks -> 32768 exact
    out[i] = 0.f;
    if (i < Gg) g_cnt[i] = 0.f;
}

__global__ void __launch_bounds__(256) k_readout(const int* __restrict__ gid,
                                                 const float* __restrict__ gamH,
                                                 const float* __restrict__ betH,
                                                 float* __restrict__ out) {
    const int i = blockIdx.x * 256 + threadIdx.x;   // exact: Nn*16 = 800000
    const int q = i & 15, n = i >> 4;
    float4 hv = ((const float4*)g_h)[i];
    const float4 hn = ((const float4*)g_hn)[i];
    const float4 g4 = ((const float4*)gamH)[q];
    const float4 b4 = ((const float4*)betH)[q];
    const float4 mu = ((const float4*)(g_bnp + 128))[q];
    const float4 iv = ((const float4*)(g_bnp + 192))[q];
    hv.x += fmaxf(0.f, g4.x * (hn.x - mu.x) * iv.x + b4.x);
    hv.y += fmaxf(0.f, g4.y * (hn.y - mu.y) * iv.y + b4.y);
    hv.z += fmaxf(0.f, g4.z * (hn.z - mu.z) * iv.z + b4.z);
    hv.w += fmaxf(0.f, g4.w * (hn.w - mu.w) * iv.w + b4.w);
    const int g = gid[n];
    atomicAdd(((float4*)out) + (size_t)g * 16 + q, hv);
    if (q == 0) atomicAdd(&g_cnt[g], 1.0f);
}

__global__ void k_div(float* __restrict__ out) {
    const int i = blockIdx.x * 256 + threadIdx.x;   // exact 32768
    out[i] /= fmaxf(g_cnt[i >> 6], 1.0f);
}

// =====================================================================
extern "C" void kernel_launch(void* const* d_in, const int* in_sizes, int n_in,
                              void* d_out, int out_size) {
    const float* nodes_feat = (const float*)d_in[0];
    const float* edges_feat = (const float*)d_in[1];
    const float* nnorm      = (const float*)d_in[2];
    const float* enorm      = (const float*)d_in[3];
    const float* W_h        = (const float*)d_in[4];
    const float* b_h        = (const float*)d_in[5];
    const float* W_e        = (const float*)d_in[6];
    const float* b_e        = (const float*)d_in[7];
    const float* Wa         = (const float*)d_in[8];
    const float* ba         = (const float*)d_in[9];
    const float* Wb         = (const float*)d_in[10];
    const float* bb         = (const float*)d_in[11];
    const float* Wc         = (const float*)d_in[12];
    const float* bc         = (const float*)d_in[13];
    const float* Wd         = (const float*)d_in[14];
    const float* bd         = (const float*)d_in[15];
    const float* We         = (const float*)d_in[16];
    const float* be         = (const float*)d_in[17];
    const float* gamma_h    = (const float*)d_in[18];
    const float* beta_h     = (const float*)d_in[19];
    const float* gamma_e    = (const float*)d_in[20];
    const float* beta_e     = (const float*)d_in[21];
    const int*   esrc       = (const int*)d_in[22];
    const int*   edst       = (const int*)d_in[23];
    const int*   gid        = (const int*)d_in[24];
    float* out = (float*)d_out;

    const int dynSmem = 4 * 4096 * 4 + 64 * 64 * 4;   // 81920 bytes
    cudaFuncSetAttribute(k_node_gemm, cudaFuncAttributeMaxDynamicSharedMemorySize, dynSmem);

    // all four Wc layers into constant memory (one 64 KB D2D copy)
    cudaMemcpyToSymbolAsync(cWc, Wc, 4 * 4096 * sizeof(float), 0,
                            cudaMemcpyDeviceToDevice, 0);                   // 1
    k_embed_h<<<(Nn + 63) / 64, 256>>>(nodes_feat, W_h, b_h);               // 2
    k_zero_out<<<128, 256>>>(out);                                          // 3

    const int NG = (Nn + 255) / 256;   // 196 blocks (256 nodes/block)
    const int EG = Ee / 256;           // 3125 blocks, thread-per-edge
    const int EC = (int)(((size_t)Ee * 16 + 255) / 256);
    for (int l = 0; l < 4; l++) {
        k_node_gemm<<<NG, 256, dynSmem>>>(
            Wa + (size_t)l * 4096, Wb + (size_t)l * 4096,
            Wd + (size_t)l * 4096, We + (size_t)l * 4096,
            ba + l * 64, bb + l * 64, bd + l * 64, be + l * 64);            // 4 (l=0)

        const float* bcL = bc + l * 64;
        if (l == 0)
            k_edge<0><<<EG, 256>>>(l, bcL, esrc, edst, enorm, edges_feat, W_e, b_e); // 5 <- profiled
        else if (l < 3)
            k_edge<1><<<EG, 256>>>(l, bcL, esrc, edst, enorm, edges_feat, W_e, b_e);
        else
            k_edge<2><<<EG, 256>>>(l, bcL, esrc, edst, enorm, edges_feat, W_e, b_e);

        k_node_B<<<1024, 256>>>(nnorm);
        k_finalize<<<1, 64>>>();
        if (l < 3) {
            k_node_C<<<(Nn * 16 + 255) / 256, 256>>>(gamma_h + l * 64, beta_h + l * 64);
            if (l == 0)
                k_edge_C<1><<<EC, 256>>>(edges_feat, W_e, b_e,
                                         gamma_e + l * 64, beta_e + l * 64);
            else
                k_edge_C<0><<<EC, 256>>>(edges_feat, W_e, b_e,
                                         gamma_e + l * 64, beta_e + l * 64);
        }
    }

    k_readout<<<Nn * 16 / 256, 256>>>(gid, gamma_h + 3 * 64, beta_h + 3 * 64, out);
    k_div<<<Gg * 64 / 256, 256>>>(out);
}